// round 2
// baseline (speedup 1.0000x reference)
#include <cuda_runtime.h>

#define HID   768
#define NROWS 512          // B*S = 4*128
#define NPAIR 384          // HID/2
#define BK    32

typedef unsigned long long ull;

// Scratch (allocation-free rule: __device__ globals)
__device__ float g_rot[2][NROWS * HID];   // rotated review / reply
__device__ float g_proj[2][NROWS * HID];  // proj_review(+bias) / proj_reply

// ---- packed fp32x2 helpers (sm_100+; ptxas never emits FFMA2 from C++) ----
__device__ __forceinline__ ull dup2(float a) {
    ull r;
    asm("mov.b64 %0, {%1, %1};" : "=l"(r) : "f"(a));
    return r;
}
__device__ __forceinline__ void fma2(ull& d, ull a, ull b) {
    asm("fma.rn.f32x2 %0, %1, %2, %0;" : "+l"(d) : "l"(a), "l"(b));
}

// ============================================================================
// 1) Rotary embedding for both inputs.
// ============================================================================
__global__ void rotary_kernel(const float* __restrict__ rev,
                              const float* __restrict__ rep) {
    int idx = blockIdx.x * 256 + threadIdx.x;       // over 2*512*384 pairs
    if (idx >= 2 * NROWS * NPAIR) return;
    int which = idx / (NROWS * NPAIR);
    int rem   = idx - which * (NROWS * NPAIR);      // row*NPAIR + i
    int row   = rem / NPAIR;
    int i     = rem - row * NPAIR;
    int s     = row & 127;                          // position within sequence

    const float2* in = (const float2*)(which ? rep : rev);
    float2 x = in[rem];

    // inv = 10000^(-2i/768) = exp(i * (-2*ln(10000)/768))
    const float cexp = -2.0f * 9.210340371976184f / 768.0f;
    float inv = __expf((float)i * cexp);
    float ang = (float)s * inv;
    float c, sn;
    sincosf(ang, &sn, &c);          // precise: angles up to ~128 rad

    float2 o;
    o.x = x.x * c - x.y * sn;
    o.y = x.y * c + x.x * sn;
    ((float2*)g_rot[which])[rem] = o;
}

// ============================================================================
// 2) GEMM v2: C[r][o] = sum_h A[r][h] * W[o][off+h]
//    Tile 32(rows) x 64(o), BK=32, 128 threads, thread tile 2x8 via FFMA2.
//    A stored pre-duplicated ({a,a} f32x2) in smem -> no movs in inner loop.
//    Grid 12 x 16 x 2 = 384 CTAs -> 2-3 CTAs/SM, balanced; latency hidden.
// ============================================================================
__global__ __launch_bounds__(128) void gemm_kernel(const float* __restrict__ W,
                                                   const float* __restrict__ bias) {
    __shared__ ull   As2[BK][32];       // duplicated A values, 8 KB
    __shared__ float Bs[BK][66];        // pad 66 -> 8.25 KB

    int t = threadIdx.x;
    int z = blockIdx.z;
    int rowBase = blockIdx.y * 32;
    int oBase   = blockIdx.x * 64;
    const float* A = g_rot[z];
    float*       C = g_proj[z];
    int off = z * HID;

    ull acc[2][4];
    #pragma unroll
    for (int i = 0; i < 2; i++)
        #pragma unroll
        for (int p = 0; p < 4; p++) acc[i][p] = 0ull;

    int ry = t >> 3, cx = t & 7;        // ry 0..15, cx 0..7
    int r0 = ry * 2, c0 = cx * 8;

    for (int k0 = 0; k0 < HID; k0 += BK) {
        // A chunk: 32 rows x 32 k = 256 float4, 2 per thread
        #pragma unroll
        for (int c = 0; c < 2; c++) {
            int idx = t + c * 128;
            int r = idx >> 3, kq = (idx & 7) * 4;
            float4 va = *(const float4*)&A[(rowBase + r) * HID + k0 + kq];
            As2[kq + 0][r] = dup2(va.x);
            As2[kq + 1][r] = dup2(va.y);
            As2[kq + 2][r] = dup2(va.z);
            As2[kq + 3][r] = dup2(va.w);
        }
        // B chunk: 64 rows(o) x 32 k = 512 float4, 4 per thread
        #pragma unroll
        for (int c = 0; c < 4; c++) {
            int idx = t + c * 128;
            int r = idx >> 3, kq = (idx & 7) * 4;
            float4 vw = *(const float4*)&W[(oBase + r) * 1536 + off + k0 + kq];
            Bs[kq + 0][r] = vw.x;
            Bs[kq + 1][r] = vw.y;
            Bs[kq + 2][r] = vw.z;
            Bs[kq + 3][r] = vw.w;
        }
        __syncthreads();

        #pragma unroll
        for (int kk = 0; kk < BK; kk++) {
            ull a0 = As2[kk][r0];
            ull a1 = As2[kk][r0 + 1];
            ull bp[4];
            #pragma unroll
            for (int p = 0; p < 4; p++) {
                float2 b2 = *(const float2*)&Bs[kk][c0 + 2 * p];
                bp[p] = *(ull*)&b2;
            }
            #pragma unroll
            for (int p = 0; p < 4; p++) {
                fma2(acc[0][p], a0, bp[p]);
                fma2(acc[1][p], a1, bp[p]);
            }
        }
        __syncthreads();
    }

    #pragma unroll
    for (int i = 0; i < 2; i++) {
        int row = rowBase + r0 + i;
        #pragma unroll
        for (int p = 0; p < 4; p++) {
            float2 v;
            asm("mov.b64 {%0, %1}, %2;" : "=f"(v.x), "=f"(v.y) : "l"(acc[i][p]));
            int col = oBase + c0 + 2 * p;
            if (z == 0) { v.x += bias[col]; v.y += bias[col + 1]; }
            *(float2*)&C[row * HID + col] = v;
        }
    }
}

// ============================================================================
// 3) Broadcast add + ReLU: out[b,n,m,:] = relu(pr[b,n,:] + pp[b,m,:])
//    8x8 (n x m) tile per block, 192 threads (one float4 column each).
//    HBM-write-bound: 201 MB of stores.
// ============================================================================
__global__ __launch_bounds__(192) void bcast_relu_kernel(float* __restrict__ out) {
    int t  = threadIdx.x;           // 0..191 : float4 column index
    int b  = blockIdx.z;
    int n0 = blockIdx.y * 8;
    int m0 = blockIdx.x * 8;

    const float4* PR = (const float4*)g_proj[0];
    const float4* PP = (const float4*)g_proj[1];

    float4 rv[8], pv[8];
    #pragma unroll
    for (int i = 0; i < 8; i++) rv[i] = PR[(b * 128 + n0 + i) * 192 + t];
    #pragma unroll
    for (int j = 0; j < 8; j++) pv[j] = PP[(b * 128 + m0 + j) * 192 + t];

    float4* O = (float4*)out;
    int base = ((b * 128 + n0) * 128 + m0) * 192 + t;

    #pragma unroll
    for (int i = 0; i < 8; i++) {
        #pragma unroll
        for (int j = 0; j < 8; j++) {
            float4 s;
            s.x = fmaxf(rv[i].x + pv[j].x, 0.0f);
            s.y = fmaxf(rv[i].y + pv[j].y, 0.0f);
            s.z = fmaxf(rv[i].z + pv[j].z, 0.0f);
            s.w = fmaxf(rv[i].w + pv[j].w, 0.0f);
            O[base + i * (128 * 192) + j * 192] = s;
        }
    }
}

// ============================================================================
// inputs (metadata order): review(4,128,768) reply(4,128,768) W(768,1536) b(768)
// output: float32 (4,128,128,768)
// ============================================================================
extern "C" void kernel_launch(void* const* d_in, const int* in_sizes, int n_in,
                              void* d_out, int out_size) {
    const float* review = (const float*)d_in[0];
    const float* reply  = (const float*)d_in[1];
    const float* W      = (const float*)d_in[2];
    const float* bias   = (const float*)d_in[3];
    float* out = (float*)d_out;

    rotary_kernel<<<1536, 256>>>(review, reply);
    gemm_kernel<<<dim3(12, 16, 2), 128>>>(W, bias);
    bcast_relu_kernel<<<dim3(16, 16, 4), 192>>>(out);
}

// round 4
// speedup vs baseline: 2.3357x; 2.3357x over previous
#include <cuda_runtime.h>
#include <cuda_bf16.h>
#include <cstdint>

#define HID    768
#define NROWS  512          // B*S = 4*128
#define CHUNKS 36           // virtual K = 36*64 = 2304 (split-2 concatenation)
#define STAGES 3
#define STG_SZ 24576        // A 8KB + W 16KB per stage
#define SMEM_TOTAL (STAGES * STG_SZ)

// ---------------------------------------------------------------------------
// Scratch (__device__ globals; no allocation allowed)
// ---------------------------------------------------------------------------
// A2[z][row][0..767] = ah (bf16 hi of rotated input), [768..1535] = al (lo)
__device__ __nv_bfloat16 g_A2[2][NROWS][1536];
// W2[z][o][0..767] = wh, [768..1535] = wl    (w = W[o][z*768 + h])
__device__ __nv_bfloat16 g_W2[2][HID][1536];
// projections fp32 (bias folded into z==0)
__device__ float g_proj[2][NROWS * HID];

// ---------------------------------------------------------------------------
#define SWZ128(o) ((o) ^ (((o) >> 3) & 0x70))

__device__ __forceinline__ uint32_t smem_u32(const void* p) {
    uint32_t a;
    asm("{ .reg .u64 t; cvta.to.shared.u64 t, %1; cvt.u32.u64 %0, t; }" : "=r"(a) : "l"(p));
    return a;
}
__device__ __forceinline__ void split_bf16(float v, __nv_bfloat16& hi, __nv_bfloat16& lo) {
    hi = __float2bfloat16_rn(v);
    lo = __float2bfloat16_rn(v - __bfloat162float(hi));
}

// ===========================================================================
// 1a) rotary + bf16 split of review/reply -> g_A2
// ===========================================================================
__global__ void rotary_split_kernel(const float* __restrict__ rev,
                                    const float* __restrict__ rep) {
    int idx = blockIdx.x * 256 + threadIdx.x;         // over 2*512*192 float4s
    if (idx >= 2 * NROWS * 192) return;
    int which = idx / (NROWS * 192);
    int rem   = idx - which * (NROWS * 192);
    int row   = rem / 192;
    int q     = rem - row * 192;                      // float4 index; k = 4q
    int s     = row & 127;

    const float4* in = (const float4*)(which ? rep : rev);
    float4 x = in[rem];

    const float cexp = -2.0f * 9.210340371976184f / 768.0f;   // -2*ln(1e4)/768
    float a0 = (float)s * __expf((float)(2 * q) * cexp);
    float a1 = (float)s * __expf((float)(2 * q + 1) * cexp);
    float c0, s0, c1, s1;
    sincosf(a0, &s0, &c0);
    sincosf(a1, &s1, &c1);

    float4 o;
    o.x = x.x * c0 - x.y * s0;
    o.y = x.y * c0 + x.x * s0;
    o.z = x.z * c1 - x.w * s1;
    o.w = x.w * c1 + x.z * s1;

    __nv_bfloat16 h[4], l[4];
    split_bf16(o.x, h[0], l[0]); split_bf16(o.y, h[1], l[1]);
    split_bf16(o.z, h[2], l[2]); split_bf16(o.w, h[3], l[3]);

    __nv_bfloat16* dst = &g_A2[which][row][0];
    *(uint2*)&dst[4 * q]       = *(uint2*)h;
    *(uint2*)&dst[768 + 4 * q] = *(uint2*)l;
}

// ===========================================================================
// 1b) bf16 split of W -> g_W2
// ===========================================================================
__global__ void wsplit_kernel(const float* __restrict__ W) {
    int idx = blockIdx.x * 256 + threadIdx.x;         // over 2*768*192 float4s
    if (idx >= 2 * HID * 192) return;
    int z   = idx / (HID * 192);
    int rem = idx - z * (HID * 192);
    int o   = rem / 192;
    int q   = rem - o * 192;

    float4 w = *(const float4*)&W[o * 1536 + z * 768 + 4 * q];
    __nv_bfloat16 h[4], l[4];
    split_bf16(w.x, h[0], l[0]); split_bf16(w.y, h[1], l[1]);
    split_bf16(w.z, h[2], l[2]); split_bf16(w.w, h[3], l[3]);

    __nv_bfloat16* dst = &g_W2[z][o][0];
    *(uint2*)&dst[4 * q]       = *(uint2*)h;
    *(uint2*)&dst[768 + 4 * q] = *(uint2*)l;
}

// ===========================================================================
// 2) mma.sync bf16 GEMM (split-2): C[512x768] per z.
//    Block 64(m) x 128(n), 8 warps (2x4), warp tile 32x32.
//    cp.async 3-stage pipeline, SW128 swizzle, ldmatrix TN (no .trans).
//    Chunks 0-11: ah*wh, 12-23: ah*wl, 24-35: al*wh.
// ===========================================================================
__global__ __launch_bounds__(256, 1) void gemm_mma_kernel(const float* __restrict__ bias) {
    extern __shared__ __align__(1024) char smem[];
    uint32_t sb = smem_u32(smem);

    int t = threadIdx.x, lane = t & 31, wid = t >> 5;
    int wm = wid >> 2, wn = wid & 3;                  // warp grid 2 x 4
    int z = blockIdx.z;
    int rowBase = blockIdx.y * 64;
    int oBase   = blockIdx.x * 128;
    const __nv_bfloat16* A2 = &g_A2[z][0][0];
    const __nv_bfloat16* W2 = &g_W2[z][0][0];

    float acc[2][4][4];
    #pragma unroll
    for (int i = 0; i < 2; i++)
        #pragma unroll
        for (int j = 0; j < 4; j++)
            #pragma unroll
            for (int r = 0; r < 4; r++) acc[i][j][r] = 0.0f;

    // ---- chunk loader: 1536 x 16B segments via cp.async ----
    auto load_chunk = [&](int c) {
        int s = c % STAGES;
        int cm = c % 12;
        int aoff = cm * 64 + ((c >= 24) ? 768 : 0);
        int woff = cm * 64 + ((c >= 12 && c < 24) ? 768 : 0);
        uint32_t stA = sb + s * STG_SZ;
        uint32_t stW = stA + 8192;
        #pragma unroll
        for (int rep = 0; rep < 6; rep++) {
            int i = t + rep * 256;
            uint32_t dst;
            const void* src;
            if (i < 512) {                            // A: 64 rows x 8 segs
                int r = i >> 3, sg = i & 7;
                dst = stA + SWZ128(r * 128 + sg * 16);
                src = &A2[(rowBase + r) * 1536 + aoff + sg * 8];
            } else {                                  // W: 128 rows x 8 segs
                int j2 = i - 512;
                int r = j2 >> 3, sg = j2 & 7;
                dst = stW + SWZ128(r * 128 + sg * 16);
                src = &W2[(oBase + r) * 1536 + woff + sg * 8];
            }
            asm volatile("cp.async.cg.shared.global [%0], [%1], 16;" :: "r"(dst), "l"(src));
        }
        asm volatile("cp.async.commit_group;" ::: "memory");
    };

    load_chunk(0);
    load_chunk(1);

    for (int c = 0; c < CHUNKS; c++) {
        if (c == CHUNKS - 1) asm volatile("cp.async.wait_group 0;" ::: "memory");
        else                 asm volatile("cp.async.wait_group 1;" ::: "memory");
        __syncthreads();
        if (c + 2 < CHUNKS) load_chunk(c + 2);

        int s = c % STAGES;
        uint32_t stA = sb + s * STG_SZ;
        uint32_t stW = stA + 8192;

        #pragma unroll
        for (int kk = 0; kk < 4; kk++) {              // 4 x k16 per 64-chunk
            uint32_t a[2][4];
            #pragma unroll
            for (int i = 0; i < 2; i++) {
                uint32_t addr = stA + SWZ128((wm * 32 + i * 16 + (lane & 15)) * 128
                                             + kk * 32 + ((lane >> 4) << 4));
                asm volatile("ldmatrix.sync.aligned.m8n8.x4.shared.b16 {%0,%1,%2,%3}, [%4];"
                             : "=r"(a[i][0]), "=r"(a[i][1]), "=r"(a[i][2]), "=r"(a[i][3])
                             : "r"(addr));
            }
            uint32_t b[4][2];
            #pragma unroll
            for (int jp = 0; jp < 2; jp++) {
                int grp = lane >> 3, jl = grp >> 1, h = grp & 1;
                uint32_t addr = stW + SWZ128((wn * 32 + jp * 16 + jl * 8 + (lane & 7)) * 128
                                             + kk * 32 + h * 16);
                uint32_t r0, r1, r2, r3;
                asm volatile("ldmatrix.sync.aligned.m8n8.x4.shared.b16 {%0,%1,%2,%3}, [%4];"
                             : "=r"(r0), "=r"(r1), "=r"(r2), "=r"(r3) : "r"(addr));
                b[jp * 2 + 0][0] = r0; b[jp * 2 + 0][1] = r1;
                b[jp * 2 + 1][0] = r2; b[jp * 2 + 1][1] = r3;
            }
            #pragma unroll
            for (int i = 0; i < 2; i++)
                #pragma unroll
                for (int j = 0; j < 4; j++)
                    asm volatile(
                        "mma.sync.aligned.m16n8k16.row.col.f32.bf16.bf16.f32 "
                        "{%0,%1,%2,%3}, {%4,%5,%6,%7}, {%8,%9}, {%0,%1,%2,%3};"
                        : "+f"(acc[i][j][0]), "+f"(acc[i][j][1]),
                          "+f"(acc[i][j][2]), "+f"(acc[i][j][3])
                        : "r"(a[i][0]), "r"(a[i][1]), "r"(a[i][2]), "r"(a[i][3]),
                          "r"(b[j][0]), "r"(b[j][1]));
        }
    }

    // ---- epilogue: fp32 accum -> g_proj (+bias on z==0) ----
    int lr = lane >> 2, lc = (lane & 3) * 2;
    float* C = g_proj[z];
    #pragma unroll
    for (int i = 0; i < 2; i++) {
        int row = rowBase + wm * 32 + i * 16 + lr;
        #pragma unroll
        for (int j = 0; j < 4; j++) {
            int col = oBase + wn * 32 + j * 8 + lc;
            float2 v0 = make_float2(acc[i][j][0], acc[i][j][1]);
            float2 v1 = make_float2(acc[i][j][2], acc[i][j][3]);
            if (z == 0) {
                float2 bv = *(const float2*)&bias[col];
                v0.x += bv.x; v0.y += bv.y;
                v1.x += bv.x; v1.y += bv.y;
            }
            *(float2*)&C[row * HID + col]       = v0;
            *(float2*)&C[(row + 8) * HID + col] = v1;
        }
    }
}

// ===========================================================================
// 3) Broadcast add + ReLU: out[b,n,m,:] = relu(pr[b,n,:] + pp[b,m,:])
//    HBM-write-bound: 201 MB of stores.
// ===========================================================================
__global__ __launch_bounds__(192) void bcast_relu_kernel(float* __restrict__ out) {
    int t  = threadIdx.x;
    int b  = blockIdx.z;
    int n0 = blockIdx.y * 8;
    int m0 = blockIdx.x * 8;

    const float4* PR = (const float4*)g_proj[0];
    const float4* PP = (const float4*)g_proj[1];

    float4 rv[8], pv[8];
    #pragma unroll
    for (int i = 0; i < 8; i++) rv[i] = PR[(b * 128 + n0 + i) * 192 + t];
    #pragma unroll
    for (int j = 0; j < 8; j++) pv[j] = PP[(b * 128 + m0 + j) * 192 + t];

    float4* O = (float4*)out;
    int base = ((b * 128 + n0) * 128 + m0) * 192 + t;

    #pragma unroll
    for (int i = 0; i < 8; i++) {
        #pragma unroll
        for (int j = 0; j < 8; j++) {
            float4 s;
            s.x = fmaxf(rv[i].x + pv[j].x, 0.0f);
            s.y = fmaxf(rv[i].y + pv[j].y, 0.0f);
            s.z = fmaxf(rv[i].z + pv[j].z, 0.0f);
            s.w = fmaxf(rv[i].w + pv[j].w, 0.0f);
            O[base + i * (128 * 192) + j * 192] = s;
        }
    }
}

// ===========================================================================
// inputs: review(4,128,768) reply(4,128,768) W(768,1536) b(768); out fp32
// ===========================================================================
extern "C" void kernel_launch(void* const* d_in, const int* in_sizes, int n_in,
                              void* d_out, int out_size) {
    const float* review = (const float*)d_in[0];
    const float* reply  = (const float*)d_in[1];
    const float* W      = (const float*)d_in[2];
    const float* bias   = (const float*)d_in[3];
    float* out = (float*)d_out;

    static bool attr_set = false;
    if (!attr_set) {
        cudaFuncSetAttribute(gemm_mma_kernel,
                             cudaFuncAttributeMaxDynamicSharedMemorySize, SMEM_TOTAL);
        attr_set = true;
    }

    rotary_split_kernel<<<768, 256>>>(review, reply);
    wsplit_kernel<<<1152, 256>>>(W);
    gemm_mma_kernel<<<dim3(6, 8, 2), 256, SMEM_TOTAL>>>(bias);
    bcast_relu_kernel<<<dim3(16, 16, 4), 192>>>(out);
}

// round 5
// speedup vs baseline: 2.8910x; 1.2378x over previous
#include <cuda_runtime.h>
#include <cuda_bf16.h>
#include <cstdint>

#define HID    768
#define NROWS  512          // B*S = 4*128
#define CHUNKS 12           // per part: K = 12*64 = 768
#define STAGES 3
#define STG_SZ 24576        // A 8KB + W 16KB per stage
#define SMEM_TOTAL (STAGES * STG_SZ)

// ---------------------------------------------------------------------------
// Scratch (__device__ globals; no allocation allowed)
// ---------------------------------------------------------------------------
__device__ __nv_bfloat16 g_A2[2][NROWS][1536];   // [0..767]=ah, [768..]=al
__device__ __nv_bfloat16 g_W2[2][HID][1536];     // [0..767]=wh, [768..]=wl
__device__ float g_part[6][NROWS * HID];         // z*3+part partial products
__device__ float g_proj[2][NROWS * HID];         // reduced (+bias on z==0)

// ---------------------------------------------------------------------------
#define SWZ128(o) ((o) ^ (((o) >> 3) & 0x70))

__device__ __forceinline__ uint32_t smem_u32(const void* p) {
    uint32_t a;
    asm("{ .reg .u64 t; cvta.to.shared.u64 t, %1; cvt.u32.u64 %0, t; }" : "=r"(a) : "l"(p));
    return a;
}
__device__ __forceinline__ void split_bf16(float v, __nv_bfloat16& hi, __nv_bfloat16& lo) {
    hi = __float2bfloat16_rn(v);
    lo = __float2bfloat16_rn(v - __bfloat162float(hi));
}

// ===========================================================================
// 1) fused prep: blocks [0,768) rotary+split of review/reply -> g_A2
//               blocks [768,1920) split of W -> g_W2
// ===========================================================================
__global__ void prep_kernel(const float* __restrict__ rev,
                            const float* __restrict__ rep,
                            const float* __restrict__ W) {
    if (blockIdx.x < 768) {
        int idx = blockIdx.x * 256 + threadIdx.x;     // 2*512*192 float4s
        int which = idx / (NROWS * 192);
        int rem   = idx - which * (NROWS * 192);
        int row   = rem / 192;
        int q     = rem - row * 192;                  // float4 index; k = 4q
        int s     = row & 127;

        const float4* in = (const float4*)(which ? rep : rev);
        float4 x = in[rem];

        const float cexp = -2.0f * 9.210340371976184f / 768.0f;
        float a0 = (float)s * __expf((float)(2 * q) * cexp);
        float a1 = (float)s * __expf((float)(2 * q + 1) * cexp);
        float c0, s0, c1, s1;
        sincosf(a0, &s0, &c0);
        sincosf(a1, &s1, &c1);

        float4 o;
        o.x = x.x * c0 - x.y * s0;
        o.y = x.y * c0 + x.x * s0;
        o.z = x.z * c1 - x.w * s1;
        o.w = x.w * c1 + x.z * s1;

        __nv_bfloat16 h[4], l[4];
        split_bf16(o.x, h[0], l[0]); split_bf16(o.y, h[1], l[1]);
        split_bf16(o.z, h[2], l[2]); split_bf16(o.w, h[3], l[3]);

        __nv_bfloat16* dst = &g_A2[which][row][0];
        *(uint2*)&dst[4 * q]       = *(uint2*)h;
        *(uint2*)&dst[768 + 4 * q] = *(uint2*)l;
    } else {
        int idx = (blockIdx.x - 768) * 256 + threadIdx.x;   // 2*768*192 float4s
        int z   = idx / (HID * 192);
        int rem = idx - z * (HID * 192);
        int o   = rem / 192;
        int q   = rem - o * 192;

        float4 w = *(const float4*)&W[o * 1536 + z * 768 + 4 * q];
        __nv_bfloat16 h[4], l[4];
        split_bf16(w.x, h[0], l[0]); split_bf16(w.y, h[1], l[1]);
        split_bf16(w.z, h[2], l[2]); split_bf16(w.w, h[3], l[3]);

        __nv_bfloat16* dst = &g_W2[z][o][0];
        *(uint2*)&dst[4 * q]       = *(uint2*)h;
        *(uint2*)&dst[768 + 4 * q] = *(uint2*)l;
    }
}

// ===========================================================================
// 2) mma.sync bf16 GEMM: one split-2 part per CTA-z slice (K=768 each).
//    Block 64(m) x 128(n), 8 warps (2x4), warp tile 32x32.
//    grid 6(n) x 8(m) x 6(z*3+part) = 288 CTAs -> 2/SM balanced wave.
//    part 0: ah*wh   part 1: ah*wl   part 2: al*wh
// ===========================================================================
__global__ __launch_bounds__(256, 2) void gemm_mma_kernel() {
    extern __shared__ __align__(1024) char smem[];
    uint32_t sb = smem_u32(smem);

    int t = threadIdx.x, lane = t & 31, wid = t >> 5;
    int wm = wid >> 2, wn = wid & 3;                  // warp grid 2 x 4
    int zp = blockIdx.z;                              // 0..5
    int z = zp >> 1 == 0 ? (zp < 3 ? 0 : 1) : (zp < 3 ? 0 : 1); // z = zp/3
    z = zp / 3;
    int part = zp - z * 3;
    int rowBase = blockIdx.y * 64;
    int oBase   = blockIdx.x * 128;
    const __nv_bfloat16* A2 = &g_A2[z][0][0];
    const __nv_bfloat16* W2 = &g_W2[z][0][0];
    int aoffBase = (part == 2) ? 768 : 0;             // al for part 2
    int woffBase = (part == 1) ? 768 : 0;             // wl for part 1

    float acc[2][4][4];
    #pragma unroll
    for (int i = 0; i < 2; i++)
        #pragma unroll
        for (int j = 0; j < 4; j++)
            #pragma unroll
            for (int r = 0; r < 4; r++) acc[i][j][r] = 0.0f;

    auto load_chunk = [&](int c) {
        int s = c % STAGES;
        int aoff = aoffBase + c * 64;
        int woff = woffBase + c * 64;
        uint32_t stA = sb + s * STG_SZ;
        uint32_t stW = stA + 8192;
        #pragma unroll
        for (int rep = 0; rep < 6; rep++) {
            int i = t + rep * 256;
            uint32_t dst;
            const void* src;
            if (i < 512) {                            // A: 64 rows x 8 segs
                int r = i >> 3, sg = i & 7;
                dst = stA + SWZ128(r * 128 + sg * 16);
                src = &A2[(rowBase + r) * 1536 + aoff + sg * 8];
            } else {                                  // W: 128 rows x 8 segs
                int j2 = i - 512;
                int r = j2 >> 3, sg = j2 & 7;
                dst = stW + SWZ128(r * 128 + sg * 16);
                src = &W2[(oBase + r) * 1536 + woff + sg * 8];
            }
            asm volatile("cp.async.cg.shared.global [%0], [%1], 16;" :: "r"(dst), "l"(src));
        }
        asm volatile("cp.async.commit_group;" ::: "memory");
    };

    load_chunk(0);
    load_chunk(1);

    for (int c = 0; c < CHUNKS; c++) {
        if (c == CHUNKS - 1) asm volatile("cp.async.wait_group 0;" ::: "memory");
        else                 asm volatile("cp.async.wait_group 1;" ::: "memory");
        __syncthreads();
        if (c + 2 < CHUNKS) load_chunk(c + 2);

        int s = c % STAGES;
        uint32_t stA = sb + s * STG_SZ;
        uint32_t stW = stA + 8192;

        #pragma unroll
        for (int kk = 0; kk < 4; kk++) {              // 4 x k16 per 64-chunk
            uint32_t a[2][4];
            #pragma unroll
            for (int i = 0; i < 2; i++) {
                uint32_t addr = stA + SWZ128((wm * 32 + i * 16 + (lane & 15)) * 128
                                             + kk * 32 + ((lane >> 4) << 4));
                asm volatile("ldmatrix.sync.aligned.m8n8.x4.shared.b16 {%0,%1,%2,%3}, [%4];"
                             : "=r"(a[i][0]), "=r"(a[i][1]), "=r"(a[i][2]), "=r"(a[i][3])
                             : "r"(addr));
            }
            uint32_t b[4][2];
            #pragma unroll
            for (int jp = 0; jp < 2; jp++) {
                int grp = lane >> 3, jl = grp >> 1, h = grp & 1;
                uint32_t addr = stW + SWZ128((wn * 32 + jp * 16 + jl * 8 + (lane & 7)) * 128
                                             + kk * 32 + h * 16);
                uint32_t r0, r1, r2, r3;
                asm volatile("ldmatrix.sync.aligned.m8n8.x4.shared.b16 {%0,%1,%2,%3}, [%4];"
                             : "=r"(r0), "=r"(r1), "=r"(r2), "=r"(r3) : "r"(addr));
                b[jp * 2 + 0][0] = r0; b[jp * 2 + 0][1] = r1;
                b[jp * 2 + 1][0] = r2; b[jp * 2 + 1][1] = r3;
            }
            #pragma unroll
            for (int i = 0; i < 2; i++)
                #pragma unroll
                for (int j = 0; j < 4; j++)
                    asm volatile(
                        "mma.sync.aligned.m16n8k16.row.col.f32.bf16.bf16.f32 "
                        "{%0,%1,%2,%3}, {%4,%5,%6,%7}, {%8,%9}, {%0,%1,%2,%3};"
                        : "+f"(acc[i][j][0]), "+f"(acc[i][j][1]),
                          "+f"(acc[i][j][2]), "+f"(acc[i][j][3])
                        : "r"(a[i][0]), "r"(a[i][1]), "r"(a[i][2]), "r"(a[i][3]),
                          "r"(b[j][0]), "r"(b[j][1]));
        }
    }

    // ---- epilogue: fp32 accum -> g_part[zp] ----
    int lr = lane >> 2, lc = (lane & 3) * 2;
    float* C = g_part[zp];
    #pragma unroll
    for (int i = 0; i < 2; i++) {
        int row = rowBase + wm * 32 + i * 16 + lr;
        #pragma unroll
        for (int j = 0; j < 4; j++) {
            int col = oBase + wn * 32 + j * 8 + lc;
            *(float2*)&C[row * HID + col] =
                make_float2(acc[i][j][0], acc[i][j][1]);
            *(float2*)&C[(row + 8) * HID + col] =
                make_float2(acc[i][j][2], acc[i][j][3]);
        }
    }
}

// ===========================================================================
// 2b) reduce: g_proj[z] = part0 + part1 + part2 (+ bias on z==0)
//     2 * 512*768 floats = 196608 float4s; L2-resident, ~2.5us
// ===========================================================================
__global__ __launch_bounds__(256) void reduce_kernel(const float* __restrict__ bias) {
    int z = blockIdx.y;
    int f = blockIdx.x * 256 + threadIdx.x;           // float4 index, < 98304
    const float4* P0 = (const float4*)g_part[z * 3 + 0];
    const float4* P1 = (const float4*)g_part[z * 3 + 1];
    const float4* P2 = (const float4*)g_part[z * 3 + 2];
    float4 a = P0[f], b = P1[f], c = P2[f];
    float4 v;
    v.x = a.x + b.x + c.x;
    v.y = a.y + b.y + c.y;
    v.z = a.z + b.z + c.z;
    v.w = a.w + b.w + c.w;
    if (z == 0) {
        float4 bv = ((const float4*)bias)[f % 192];
        v.x += bv.x; v.y += bv.y; v.z += bv.z; v.w += bv.w;
    }
    ((float4*)g_proj[z])[f] = v;
}

// ===========================================================================
// 3) Broadcast add + ReLU: out[b,n,m,:] = relu(pr[b,n,:] + pp[b,m,:])
//    Streaming stores (write-once output). HBM-write-bound: 201 MB.
// ===========================================================================
__global__ __launch_bounds__(192) void bcast_relu_kernel(float* __restrict__ out) {
    int t  = threadIdx.x;
    int b  = blockIdx.z;
    int n0 = blockIdx.y * 8;
    int m0 = blockIdx.x * 8;

    const float4* PR = (const float4*)g_proj[0];
    const float4* PP = (const float4*)g_proj[1];

    float4 rv[8], pv[8];
    #pragma unroll
    for (int i = 0; i < 8; i++) rv[i] = PR[(b * 128 + n0 + i) * 192 + t];
    #pragma unroll
    for (int j = 0; j < 8; j++) pv[j] = PP[(b * 128 + m0 + j) * 192 + t];

    float4* O = (float4*)out;
    int base = ((b * 128 + n0) * 128 + m0) * 192 + t;

    #pragma unroll
    for (int i = 0; i < 8; i++) {
        #pragma unroll
        for (int j = 0; j < 8; j++) {
            float4 s;
            s.x = fmaxf(rv[i].x + pv[j].x, 0.0f);
            s.y = fmaxf(rv[i].y + pv[j].y, 0.0f);
            s.z = fmaxf(rv[i].z + pv[j].z, 0.0f);
            s.w = fmaxf(rv[i].w + pv[j].w, 0.0f);
            __stcs(&O[base + i * (128 * 192) + j * 192], s);
        }
    }
}

// ===========================================================================
// inputs: review(4,128,768) reply(4,128,768) W(768,1536) b(768); out fp32
// ===========================================================================
extern "C" void kernel_launch(void* const* d_in, const int* in_sizes, int n_in,
                              void* d_out, int out_size) {
    const float* review = (const float*)d_in[0];
    const float* reply  = (const float*)d_in[1];
    const float* W      = (const float*)d_in[2];
    const float* bias   = (const float*)d_in[3];
    float* out = (float*)d_out;

    static bool attr_set = false;
    if (!attr_set) {
        cudaFuncSetAttribute(gemm_mma_kernel,
                             cudaFuncAttributeMaxDynamicSharedMemorySize, SMEM_TOTAL);
        attr_set = true;
    }

    prep_kernel<<<1920, 256>>>(review, reply, W);
    gemm_mma_kernel<<<dim3(6, 8, 6), 256, SMEM_TOTAL>>>();
    reduce_kernel<<<dim3(384, 2), 256>>>(bias);
    bcast_relu_kernel<<<dim3(16, 16, 4), 192>>>(out);
}

// round 7
// speedup vs baseline: 3.0181x; 1.0440x over previous
#include <cuda_runtime.h>
#include <cuda_bf16.h>
#include <cstdint>

#define HID    768
#define NROWS  512          // B*S = 4*128
#define CHUNKS 12           // per part: K = 12*64 = 768
#define STAGES 3
#define STG_SZ 24576        // A 8KB + W 16KB per stage
#define SMEM_TOTAL (STAGES * STG_SZ)

// ---------------------------------------------------------------------------
// Scratch (__device__ globals; no allocation allowed)
// ---------------------------------------------------------------------------
__device__ __nv_bfloat16 g_A2[2][NROWS][1536];   // [0..767]=ah, [768..]=al
__device__ __nv_bfloat16 g_W2[2][HID][1536];     // [0..767]=wh, [768..]=wl
__device__ float g_part[6][NROWS * HID];         // z*3+part partial products
__device__ float g_proj[2][NROWS * HID];         // reduced (+bias on z==0)

// ---------------------------------------------------------------------------
#define SWZ128(o) ((o) ^ (((o) >> 3) & 0x70))

__device__ __forceinline__ uint32_t smem_u32(const void* p) {
    uint32_t a;
    asm("{ .reg .u64 t; cvta.to.shared.u64 t, %1; cvt.u32.u64 %0, t; }" : "=r"(a) : "l"(p));
    return a;
}
__device__ __forceinline__ void split_bf16(float v, __nv_bfloat16& hi, __nv_bfloat16& lo) {
    hi = __float2bfloat16_rn(v);
    lo = __float2bfloat16_rn(v - __bfloat162float(hi));
}

// ===========================================================================
// 1) fused prep: blocks [0,768) rotary+split of review/reply -> g_A2
//               blocks [768,1920) split of W -> g_W2
// ===========================================================================
__global__ void prep_kernel(const float* __restrict__ rev,
                            const float* __restrict__ rep,
                            const float* __restrict__ W) {
    if (blockIdx.x < 768) {
        int idx = blockIdx.x * 256 + threadIdx.x;     // 2*512*192 float4s
        int which = idx / (NROWS * 192);
        int rem   = idx - which * (NROWS * 192);
        int row   = rem / 192;
        int q     = rem - row * 192;                  // float4 index; k = 4q
        int s     = row & 127;

        const float4* in = (const float4*)(which ? rep : rev);
        float4 x = in[rem];

        const float cexp = -2.0f * 9.210340371976184f / 768.0f;
        float a0 = (float)s * __expf((float)(2 * q) * cexp);
        float a1 = (float)s * __expf((float)(2 * q + 1) * cexp);
        float c0, s0, c1, s1;
        sincosf(a0, &s0, &c0);
        sincosf(a1, &s1, &c1);

        float4 o;
        o.x = x.x * c0 - x.y * s0;
        o.y = x.y * c0 + x.x * s0;
        o.z = x.z * c1 - x.w * s1;
        o.w = x.w * c1 + x.z * s1;

        __nv_bfloat16 h[4], l[4];
        split_bf16(o.x, h[0], l[0]); split_bf16(o.y, h[1], l[1]);
        split_bf16(o.z, h[2], l[2]); split_bf16(o.w, h[3], l[3]);

        __nv_bfloat16* dst = &g_A2[which][row][0];
        *(uint2*)&dst[4 * q]       = *(uint2*)h;
        *(uint2*)&dst[768 + 4 * q] = *(uint2*)l;
    } else {
        int idx = (blockIdx.x - 768) * 256 + threadIdx.x;   // 2*768*192 float4s
        int z   = idx / (HID * 192);
        int rem = idx - z * (HID * 192);
        int o   = rem / 192;
        int q   = rem - o * 192;

        float4 w = *(const float4*)&W[o * 1536 + z * 768 + 4 * q];
        __nv_bfloat16 h[4], l[4];
        split_bf16(w.x, h[0], l[0]); split_bf16(w.y, h[1], l[1]);
        split_bf16(w.z, h[2], l[2]); split_bf16(w.w, h[3], l[3]);

        __nv_bfloat16* dst = &g_W2[z][o][0];
        *(uint2*)&dst[4 * q]       = *(uint2*)h;
        *(uint2*)&dst[768 + 4 * q] = *(uint2*)l;
    }
}

// ===========================================================================
// 2) mma.sync bf16 GEMM: one split-2 part per CTA-z slice (K=768 each).
//    Block 64(m) x 128(n), 8 warps (2x4), warp tile 32x32.
//    grid 6(n) x 8(m) x 6(z*3+part) = 288 CTAs -> 2/SM balanced wave.
// ===========================================================================
__global__ __launch_bounds__(256, 2) void gemm_mma_kernel() {
    extern __shared__ __align__(1024) char smem[];
    uint32_t sb = smem_u32(smem);

    int t = threadIdx.x, lane = t & 31, wid = t >> 5;
    int wm = wid >> 2, wn = wid & 3;                  // warp grid 2 x 4
    int zp = blockIdx.z;                              // 0..5
    int z = zp / 3;
    int part = zp - z * 3;
    int rowBase = blockIdx.y * 64;
    int oBase   = blockIdx.x * 128;
    const __nv_bfloat16* A2 = &g_A2[z][0][0];
    const __nv_bfloat16* W2 = &g_W2[z][0][0];
    int aoffBase = (part == 2) ? 768 : 0;             // al for part 2
    int woffBase = (part == 1) ? 768 : 0;             // wl for part 1

    float acc[2][4][4];
    #pragma unroll
    for (int i = 0; i < 2; i++)
        #pragma unroll
        for (int j = 0; j < 4; j++)
            #pragma unroll
            for (int r = 0; r < 4; r++) acc[i][j][r] = 0.0f;

    auto load_chunk = [&](int c) {
        int s = c % STAGES;
        int aoff = aoffBase + c * 64;
        int woff = woffBase + c * 64;
        uint32_t stA = sb + s * STG_SZ;
        uint32_t stW = stA + 8192;
        #pragma unroll
        for (int rep = 0; rep < 6; rep++) {
            int i = t + rep * 256;
            uint32_t dst;
            const void* src;
            if (i < 512) {                            // A: 64 rows x 8 segs
                int r = i >> 3, sg = i & 7;
                dst = stA + SWZ128(r * 128 + sg * 16);
                src = &A2[(rowBase + r) * 1536 + aoff + sg * 8];
            } else {                                  // W: 128 rows x 8 segs
                int j2 = i - 512;
                int r = j2 >> 3, sg = j2 & 7;
                dst = stW + SWZ128(r * 128 + sg * 16);
                src = &W2[(oBase + r) * 1536 + woff + sg * 8];
            }
            asm volatile("cp.async.cg.shared.global [%0], [%1], 16;" :: "r"(dst), "l"(src));
        }
        asm volatile("cp.async.commit_group;" ::: "memory");
    };

    load_chunk(0);
    load_chunk(1);

    for (int c = 0; c < CHUNKS; c++) {
        if (c == CHUNKS - 1) asm volatile("cp.async.wait_group 0;" ::: "memory");
        else                 asm volatile("cp.async.wait_group 1;" ::: "memory");
        __syncthreads();
        if (c + 2 < CHUNKS) load_chunk(c + 2);

        int s = c % STAGES;
        uint32_t stA = sb + s * STG_SZ;
        uint32_t stW = stA + 8192;

        #pragma unroll
        for (int kk = 0; kk < 4; kk++) {              // 4 x k16 per 64-chunk
            uint32_t a[2][4];
            #pragma unroll
            for (int i = 0; i < 2; i++) {
                uint32_t addr = stA + SWZ128((wm * 32 + i * 16 + (lane & 15)) * 128
                                             + kk * 32 + ((lane >> 4) << 4));
                asm volatile("ldmatrix.sync.aligned.m8n8.x4.shared.b16 {%0,%1,%2,%3}, [%4];"
                             : "=r"(a[i][0]), "=r"(a[i][1]), "=r"(a[i][2]), "=r"(a[i][3])
                             : "r"(addr));
            }
            uint32_t b[4][2];
            #pragma unroll
            for (int jp = 0; jp < 2; jp++) {
                int grp = lane >> 3, jl = grp >> 1, h = grp & 1;
                uint32_t addr = stW + SWZ128((wn * 32 + jp * 16 + jl * 8 + (lane & 7)) * 128
                                             + kk * 32 + h * 16);
                uint32_t r0, r1, r2, r3;
                asm volatile("ldmatrix.sync.aligned.m8n8.x4.shared.b16 {%0,%1,%2,%3}, [%4];"
                             : "=r"(r0), "=r"(r1), "=r"(r2), "=r"(r3) : "r"(addr));
                b[jp * 2 + 0][0] = r0; b[jp * 2 + 0][1] = r1;
                b[jp * 2 + 1][0] = r2; b[jp * 2 + 1][1] = r3;
            }
            #pragma unroll
            for (int i = 0; i < 2; i++)
                #pragma unroll
                for (int j = 0; j < 4; j++)
                    asm volatile(
                        "mma.sync.aligned.m16n8k16.row.col.f32.bf16.bf16.f32 "
                        "{%0,%1,%2,%3}, {%4,%5,%6,%7}, {%8,%9}, {%0,%1,%2,%3};"
                        : "+f"(acc[i][j][0]), "+f"(acc[i][j][1]),
                          "+f"(acc[i][j][2]), "+f"(acc[i][j][3])
                        : "r"(a[i][0]), "r"(a[i][1]), "r"(a[i][2]), "r"(a[i][3]),
                          "r"(b[j][0]), "r"(b[j][1]));
        }
    }

    // ---- epilogue: fp32 accum -> g_part[zp] ----
    int lr = lane >> 2, lc = (lane & 3) * 2;
    float* C = g_part[zp];
    #pragma unroll
    for (int i = 0; i < 2; i++) {
        int row = rowBase + wm * 32 + i * 16 + lr;
        #pragma unroll
        for (int j = 0; j < 4; j++) {
            int col = oBase + wn * 32 + j * 8 + lc;
            *(float2*)&C[row * HID + col] =
                make_float2(acc[i][j][0], acc[i][j][1]);
            *(float2*)&C[(row + 8) * HID + col] =
                make_float2(acc[i][j][2], acc[i][j][3]);
        }
    }
}

// ===========================================================================
// 2b) reduce: g_proj[z] = part0 + part1 + part2 (+ bias on z==0)
// ===========================================================================
__global__ __launch_bounds__(256) void reduce_kernel(const float* __restrict__ bias) {
    int z = blockIdx.y;
    int f = blockIdx.x * 256 + threadIdx.x;           // float4 index, < 98304
    const float4* P0 = (const float4*)g_part[z * 3 + 0];
    const float4* P1 = (const float4*)g_part[z * 3 + 1];
    const float4* P2 = (const float4*)g_part[z * 3 + 2];
    float4 a = P0[f], b = P1[f], c = P2[f];
    float4 v;
    v.x = a.x + b.x + c.x;
    v.y = a.y + b.y + c.y;
    v.z = a.z + b.z + c.z;
    v.w = a.w + b.w + c.w;
    if (z == 0) {
        float4 bv = ((const float4*)bias)[f % 192];
        v.x += bv.x; v.y += bv.y; v.z += bv.z; v.w += bv.w;
    }
    ((float4*)g_proj[z])[f] = v;
}

// ===========================================================================
// 3) Broadcast add + ReLU: out[b,n,m,:] = relu(pr[b,n,:] + pp[b,m,:])
//    4x4 (n x m) tile, ~48 regs -> ~66% occupancy for store MLP.
//    HBM-write-bound: 201 MB of stores.
// ===========================================================================
__global__ __launch_bounds__(192) void bcast_relu_kernel(float* __restrict__ out) {
    int t  = threadIdx.x;           // 0..191 : float4 column index
    int b  = blockIdx.z;
    int n0 = blockIdx.y * 4;
    int m0 = blockIdx.x * 4;

    const float4* PR = (const float4*)g_proj[0];
    const float4* PP = (const float4*)g_proj[1];

    float4 rv[4], pv[4];
    #pragma unroll
    for (int i = 0; i < 4; i++) rv[i] = PR[(b * 128 + n0 + i) * 192 + t];
    #pragma unroll
    for (int j = 0; j < 4; j++) pv[j] = PP[(b * 128 + m0 + j) * 192 + t];

    float4* O = (float4*)out;
    int base = ((b * 128 + n0) * 128 + m0) * 192 + t;

    #pragma unroll
    for (int i = 0; i < 4; i++) {
        #pragma unroll
        for (int j = 0; j < 4; j++) {
            float4 s;
            s.x = fmaxf(rv[i].x + pv[j].x, 0.0f);
            s.y = fmaxf(rv[i].y + pv[j].y, 0.0f);
            s.z = fmaxf(rv[i].z + pv[j].z, 0.0f);
            s.w = fmaxf(rv[i].w + pv[j].w, 0.0f);
            __stcs(&O[base + i * (128 * 192) + j * 192], s);
        }
    }
}

// ===========================================================================
// inputs: review(4,128,768) reply(4,128,768) W(768,1536) b(768); out fp32
// ===========================================================================
extern "C" void kernel_launch(void* const* d_in, const int* in_sizes, int n_in,
                              void* d_out, int out_size) {
    const float* review = (const float*)d_in[0];
    const float* reply  = (const float*)d_in[1];
    const float* W      = (const float*)d_in[2];
    const float* bias   = (const float*)d_in[3];
    float* out = (float*)d_out;

    static bool attr_set = false;
    if (!attr_set) {
        cudaFuncSetAttribute(gemm_mma_kernel,
                             cudaFuncAttributeMaxDynamicSharedMemorySize, SMEM_TOTAL);
        attr_set = true;
    }

    prep_kernel<<<1920, 256>>>(review, reply, W);
    gemm_mma_kernel<<<dim3(6, 8, 6), 256, SMEM_TOTAL>>>();
    reduce_kernel<<<dim3(384, 2), 256>>>(bias);
    bcast_relu_kernel<<<dim3(32, 32, 4), 192>>>(out);
}